// round 15
// baseline (speedup 1.0000x reference)
#include <cuda_runtime.h>
#include <cuda_bf16.h>
#include <cstdint>
#include <float.h>

// Problem constants
#define N_ROWS  (64 * 2048)   // 131072
#define DDIM    128
#define KCODES  1024

// Output layout (fp32, concatenated in reference return order)
#define Q_OFF    ((size_t)0)
#define IND_OFF  ((size_t)16777216)
#define EMB_OFF  ((size_t)16908288)
#define NCS_OFF  ((size_t)17039360)
#define NEA_OFF  ((size_t)17040384)

#define DECAYF   0.99f
#define OMDF     0.01f
#define EPSF     1e-5f
#define KEPSF    0.01024f

#define SCREEN_T 0.6f
#define CAND_CAP 64

// ---------------------------------------------------------------------------
// Scratch (__device__ globals; no allocation allowed)
__device__ float    g_counts[KCODES];
__device__ float    g_embed_sum[KCODES * DDIM];
__device__ float    g_ee[KCODES];
__device__ uint4    g_E16[KCODES * 16];   // bf16 E, XOR-swizzled 16B units (256 KB)

// ---------------------------------------------------------------------------
__global__ void k_zero() {
    const int i = blockIdx.x * blockDim.x + threadIdx.x;   // 512*256 = 131072
    g_embed_sum[i] = 0.0f;
    if (i < KCODES) g_counts[i] = 0.0f;
}

// Per-code squared norms. 4 codes per block.
__global__ void k_ee(const float* __restrict__ embed) {
    const int k = blockIdx.x * 4 + (threadIdx.x >> 7);
    const int t = threadIdx.x & 127;
    float v = embed[(size_t)k * DDIM + t];
    v *= v;
    __shared__ float s[16];
    #pragma unroll
    for (int o = 16; o > 0; o >>= 1) v += __shfl_down_sync(0xffffffffu, v, o);
    if ((t & 31) == 0) s[threadIdx.x >> 5] = v;
    __syncthreads();
    if (t == 0) {
        const int b = (threadIdx.x >> 7) * 4;
        g_ee[k] = s[b] + s[b + 1] + s[b + 2] + s[b + 3];
    }
}

// Pack E into bf16 with per-row XOR swizzle on 16B units.
__global__ void k_packE(const float* __restrict__ embed) {
    const int idx = blockIdx.x * blockDim.x + threadIdx.x;  // 16384
    const int r = idx >> 4;
    const int u = idx & 15;
    const float* src = embed + (size_t)r * DDIM + u * 8;
    float4 a = ((const float4*)src)[0];
    float4 b = ((const float4*)src)[1];
    __nv_bfloat162 p0 = __float22bfloat162_rn(make_float2(a.x, a.y));
    __nv_bfloat162 p1 = __float22bfloat162_rn(make_float2(a.z, a.w));
    __nv_bfloat162 p2 = __float22bfloat162_rn(make_float2(b.x, b.y));
    __nv_bfloat162 p3 = __float22bfloat162_rn(make_float2(b.z, b.w));
    uint4 o4;
    o4.x = *(uint32_t*)&p0; o4.y = *(uint32_t*)&p1;
    o4.z = *(uint32_t*)&p2; o4.w = *(uint32_t*)&p3;
    g_E16[r * 16 + (u ^ (r & 7))] = o4;
}

// ---------------------------------------------------------------------------
__device__ __forceinline__ uint32_t smem_u32(const void* p) {
    uint32_t a;
    asm("{ .reg .u64 t; cvta.to.shared.u64 t, %1; cvt.u32.u64 %0, t; }" : "=r"(a) : "l"(p));
    return a;
}

#define MMA_BF16(accp, af, bb0, bb1) \
    asm volatile( \
        "mma.sync.aligned.m16n8k16.row.col.f32.bf16.bf16.f32 " \
        "{%0,%1,%2,%3}, {%4,%5,%6,%7}, {%8,%9}, {%0,%1,%2,%3};" \
        : "+f"((accp)[0]), "+f"((accp)[1]), "+f"((accp)[2]), "+f"((accp)[3]) \
        : "r"((af)[0]), "r"((af)[1]), "r"((af)[2]), "r"((af)[3]), \
          "r"(bb0), "r"(bb1))

// MMA over one 16-code batch, TWO m-tiles (32 rows): fills acc[2][2][4].
// B fragments shared across m-tiles -> 4 independent chains, no extra B regs.
#define BATCH_MMA(b) \
    { \
        const uint32_t rowaddr = smEb + (((b) * 16 + ctile * 8 + row8) << 8); \
        _Pragma("unroll") \
        for (int t2 = 0; t2 < 2; t2++) \
            _Pragma("unroll") \
            for (int n2 = 0; n2 < 2; n2++) \
                _Pragma("unroll") \
                for (int i = 0; i < 4; i++) acc[t2][n2][i] = 0.0f; \
        _Pragma("unroll") \
        for (int ks = 0; ks < 8; ks++) { \
            uint32_t b0, b1, b2, b3; \
            asm volatile( \
                "ldmatrix.sync.aligned.m8n8.x4.shared.b16 {%0,%1,%2,%3}, [%4];" \
                : "=r"(b0), "=r"(b1), "=r"(b2), "=r"(b3) \
                : "r"(rowaddr + (((2 * ks + khalf) ^ row8) << 4))); \
            MMA_BF16(acc[0][0], afr[0][ks], b0, b1); \
            MMA_BF16(acc[0][1], afr[0][ks], b2, b3); \
            MMA_BF16(acc[1][0], afr[1][ks], b0, b1); \
            MMA_BF16(acc[1][1], afr[1][ks], b2, b3); \
        } \
    }

// Scores for m-tile t2 into sc[2][4]
#define BATCH_SCORES(b, t2) \
    _Pragma("unroll") \
    for (int n2 = 0; n2 < 2; n2++) { \
        const float2 ee = sEE2[buf][(b) * 8 + n2 * 4 + tig]; \
        sc[0][n2 * 2 + 0] = fmaf(2.0f, acc[t2][n2][0], -ee.x); \
        sc[0][n2 * 2 + 1] = fmaf(2.0f, acc[t2][n2][1], -ee.y); \
        sc[1][n2 * 2 + 0] = fmaf(2.0f, acc[t2][n2][2], -ee.x); \
        sc[1][n2 * 2 + 1] = fmaf(2.0f, acc[t2][n2][3], -ee.y); \
    }

// Prefetch chunk ch into buffer bf (cp.async, 4x16B per thread + sEE pairs)
#define PREFETCH(ch, bf) \
    { \
        const uint32_t dst = smEbase + (bf) * 16384 + (uint32_t)tid * 16; \
        const uint4* srcp = g_E16 + (ch) * 1024 + tid; \
        _Pragma("unroll") \
        for (int i = 0; i < 4; i++) \
            asm volatile("cp.async.cg.shared.global [%0], [%1], 16;" \
                         :: "r"(dst + i * 4096), "l"(srcp + i * 256) : "memory"); \
        if (tid < 32) sEE2[bf][tid] = ((const float2*)(g_ee + (ch) * 64))[tid]; \
        asm volatile("cp.async.commit_group;" ::: "memory"); \
    }

// ---------------------------------------------------------------------------
// HMMA two-level screening + quad-cooperative exact fp32 rescore + fused
// quantized write and EMA scatter. Double-buffered cp.async E staging.
// CTA = 256 threads (8 warps), each warp owns 32 rows -> CTA covers 256 rows.
__global__ __launch_bounds__(256, 2) void k_score(const float* __restrict__ x,
                                                  const float* __restrict__ embed,
                                                  float* __restrict__ out) {
    __shared__ __align__(16) uint4 smE[2][1024];    // 2 x 16 KB E tiles
    __shared__ float2    sEE2[2][32];
    __shared__ uint16_t  sCand[256 * CAND_CAP];     // 32 KB
    __shared__ uint32_t  sCnt[256];
    __shared__ int       fidx[256];

    const int tid  = threadIdx.x;
    const int wid  = tid >> 5;
    const int lane = tid & 31;
    const int g    = lane >> 2;
    const int tig  = lane & 3;
    const int rbase = blockIdx.x * 256 + wid * 32;

    sCnt[tid] = 0;

    const uint32_t smEbase = smem_u32(smE);

    // Prologue: prefetch chunk 0 into buffer 0.
    PREFETCH(0, 0);

    // Build A fragments from x (fp32 -> bf16x2). 2 m-tiles x 8 k-steps x 4.
    uint32_t afr[2][8][4];
    #pragma unroll
    for (int t2 = 0; t2 < 2; t2++) {
        const float* xr0 = x + (size_t)(rbase + t2 * 16 + g) * DDIM + 2 * tig;
        const float* xr1 = xr0 + 8 * DDIM;
        #pragma unroll
        for (int ks = 0; ks < 8; ks++) {
            const float2 v0 = *(const float2*)(xr0 + 16 * ks);
            const float2 v1 = *(const float2*)(xr1 + 16 * ks);
            const float2 v2 = *(const float2*)(xr0 + 16 * ks + 8);
            const float2 v3 = *(const float2*)(xr1 + 16 * ks + 8);
            __nv_bfloat162 b0 = __float22bfloat162_rn(v0);
            __nv_bfloat162 b1 = __float22bfloat162_rn(v1);
            __nv_bfloat162 b2 = __float22bfloat162_rn(v2);
            __nv_bfloat162 b3 = __float22bfloat162_rn(v3);
            afr[t2][ks][0] = *(uint32_t*)&b0;
            afr[t2][ks][1] = *(uint32_t*)&b1;
            afr[t2][ks][2] = *(uint32_t*)&b2;
            afr[t2][ks][3] = *(uint32_t*)&b3;
        }
    }

    float rmax[4];   // [t2*2 + h]
    #pragma unroll
    for (int i = 0; i < 4; i++) rmax[i] = -FLT_MAX;

    const int row8  = lane & 7;
    const int ctile = (lane >> 4) & 1;
    const int khalf = (lane >> 3) & 1;

    for (int c = 0; c < 16; c++) {    // 16 chunks of 64 codes
        const int buf = c & 1;
        asm volatile("cp.async.wait_group 0;" ::: "memory");
        __syncthreads();              // buffer `buf` ready; buffer buf^1 free
        if (c < 15) PREFETCH(c + 1, buf ^ 1);

        const uint32_t smEb = smEbase + buf * 16384;
        float acc[2][2][4];
        float sc[2][4];

        if (c == 0) {
            // Max-only warm-up over chunk 0 (no appends).
            #pragma unroll
            for (int b = 0; b < 4; b++) {
                BATCH_MMA(b);
                #pragma unroll
                for (int t2 = 0; t2 < 2; t2++) {
                    BATCH_SCORES(b, t2);
                    #pragma unroll
                    for (int h = 0; h < 2; h++)
                        rmax[t2 * 2 + h] =
                            fmaxf(rmax[t2 * 2 + h],
                                  fmaxf(fmaxf(sc[h][0], sc[h][1]),
                                        fmaxf(sc[h][2], sc[h][3])));
                }
            }
            #pragma unroll
            for (int i = 0; i < 4; i++) {
                float v = rmax[i];
                v = fmaxf(v, __shfl_xor_sync(0xffffffffu, v, 1));
                v = fmaxf(v, __shfl_xor_sync(0xffffffffu, v, 2));
                rmax[i] = v;
            }
        }

        #pragma unroll
        for (int b = 0; b < 4; b++) {
            BATCH_MMA(b);

            #pragma unroll
            for (int t2 = 0; t2 < 2; t2++) {
                BATCH_SCORES(b, t2);
                #pragma unroll
                for (int h = 0; h < 2; h++) {
                    const int ci = t2 * 2 + h;
                    const float thr = rmax[ci] - SCREEN_T;
                    const float m = fmaxf(fmaxf(sc[h][0], sc[h][1]),
                                          fmaxf(sc[h][2], sc[h][3]));
                    if (m >= thr) {    // rare
                        const int lr = wid * 32 + t2 * 16 + h * 8 + g;
                        #pragma unroll
                        for (int n2 = 0; n2 < 2; n2++)
                            #pragma unroll
                            for (int j = 0; j < 2; j++)
                                if (sc[h][n2 * 2 + j] >= thr) {
                                    uint32_t n = atomicAdd(&sCnt[lr], 1u);
                                    if (n < CAND_CAP)
                                        sCand[lr * CAND_CAP + n] =
                                            (uint16_t)(c * 64 + b * 16 + n2 * 8 + 2 * tig + j);
                                }
                    }
                    rmax[ci] = fmaxf(rmax[ci], m);
                }
            }
        }

        #pragma unroll
        for (int i = 0; i < 4; i++) {
            float v = rmax[i];
            v = fmaxf(v, __shfl_xor_sync(0xffffffffu, v, 1));
            v = fmaxf(v, __shfl_xor_sync(0xffffffffu, v, 2));
            rmax[i] = v;
        }
    }
    __syncthreads();

    // Exact fp32 rescore: 8-lane quad per candidate.
    // dist' = 2*dot - ee (the -xx term is row-constant: argmax-equivalent).
    {
        const int ql = lane & 7;
        const int q  = lane >> 3;
        for (int rr = 0; rr < 32; rr++) {
            const int lr  = wid * 32 + rr;
            const int row = blockIdx.x * 256 + lr;
            const int cnt = (int)sCnt[lr];

            float bestv = -FLT_MAX;
            int   bestk = 0x7FFFFFFF;

            if (cnt <= CAND_CAP) {
                float4 xa[4];
                const float4* xr = (const float4*)(x + (size_t)row * DDIM);
                #pragma unroll
                for (int it = 0; it < 4; it++) xa[it] = xr[it * 8 + ql];

                for (int j0 = 0; j0 < cnt; j0 += 4) {
                    const int j  = j0 + q;
                    const int jc = (j < cnt) ? j : (cnt - 1);
                    const int kq = sCand[lr * CAND_CAP + jc];
                    const float4* er = (const float4*)(embed + (size_t)kq * DDIM);
                    float a0 = 0.f, a1 = 0.f, a2 = 0.f, a3 = 0.f;
                    #pragma unroll
                    for (int it = 0; it < 4; it++) {
                        const float4 ea = er[it * 8 + ql];
                        a0 = fmaf(xa[it].x, ea.x, a0);
                        a1 = fmaf(xa[it].y, ea.y, a1);
                        a2 = fmaf(xa[it].z, ea.z, a2);
                        a3 = fmaf(xa[it].w, ea.w, a3);
                    }
                    float part = (a0 + a1) + (a2 + a3);
                    part += __shfl_xor_sync(0xffffffffu, part, 1);
                    part += __shfl_xor_sync(0xffffffffu, part, 2);
                    part += __shfl_xor_sync(0xffffffffu, part, 4);
                    const float dist = 2.0f * part - g_ee[kq];
                    if (j < cnt &&
                        (dist > bestv || (dist == bestv && kq < bestk))) {
                        bestv = dist; bestk = kq;
                    }
                }
            } else {
                const float4* xr = (const float4*)(x + (size_t)row * DDIM);
                for (int k = lane; k < KCODES; k += 32) {
                    const float4* er = (const float4*)(embed + (size_t)k * DDIM);
                    float a0 = 0.f, a1 = 0.f, a2 = 0.f, a3 = 0.f;
                    #pragma unroll 8
                    for (int i = 0; i < 32; i++) {
                        float4 va = xr[i], ea = er[i];
                        a0 = fmaf(va.x, ea.x, a0);
                        a1 = fmaf(va.y, ea.y, a1);
                        a2 = fmaf(va.z, ea.z, a2);
                        a3 = fmaf(va.w, ea.w, a3);
                    }
                    const float dist = 2.0f * ((a0 + a1) + (a2 + a3)) - g_ee[k];
                    if (dist > bestv || (dist == bestv && k < bestk)) {
                        bestv = dist; bestk = k;
                    }
                }
                #pragma unroll
                for (int o = 1; o <= 4; o <<= 1) {
                    const float ov = __shfl_xor_sync(0xffffffffu, bestv, o);
                    const int   ok = __shfl_xor_sync(0xffffffffu, bestk, o);
                    if (ov > bestv || (ov == bestv && ok < bestk)) { bestv = ov; bestk = ok; }
                }
            }

            #pragma unroll
            for (int o = 8; o <= 16; o <<= 1) {
                const float ov = __shfl_xor_sync(0xffffffffu, bestv, o);
                const int   ok = __shfl_xor_sync(0xffffffffu, bestk, o);
                if (ov > bestv || (ov == bestv && ok < bestk)) { bestv = ov; bestk = ok; }
            }
            if (lane == 0) fidx[lr] = bestk;
        }
    }
    __syncthreads();

    // Coalesced embed_ind write from fidx.
    out[IND_OFF + (size_t)(blockIdx.x * 256 + tid)] = (float)fidx[tid];

    // Fused epilogue: quantized = embed[idx] write + EMA scatter (RED).
    for (int v = tid; v < 256 * 32; v += 256) {
        const int r = v >> 5, seg = v & 31;
        const int idx = fidx[r];
        const float4* ep = (const float4*)(embed + (size_t)idx * DDIM);
        ((float4*)out)[(size_t)(blockIdx.x * 256 + r) * 32 + seg] = ep[seg];

        const float4 xv =
            ((const float4*)(x + (size_t)(blockIdx.x * 256 + r) * DDIM))[seg];
        float* dst = &g_embed_sum[(size_t)idx * DDIM + seg * 4];
        asm volatile("red.global.add.v4.f32 [%0], {%1,%2,%3,%4};"
                     :: "l"(dst), "f"(xv.x), "f"(xv.y), "f"(xv.z), "f"(xv.w)
                     : "memory");
    }
    atomicAdd(&g_counts[fidx[tid]], 1.0f);
}

// ---------------------------------------------------------------------------
// Final epilogue: new_cluster_size (+ redundant per-block total), new_embed_avg,
// new_embed. Block k handles code k.
__global__ void k_cfin(const float* __restrict__ cs,
                       const float* __restrict__ ea,
                       float* __restrict__ out) {
    const int k = blockIdx.x;    // 1024
    const int d = threadIdx.x;   // 128

    float part = 0.0f;
    #pragma unroll
    for (int i = 0; i < 8; i++) {
        const int j = d + i * 128;
        part += cs[j] * DECAYF + OMDF * g_counts[j];
    }
    #pragma unroll
    for (int o = 16; o > 0; o >>= 1) part += __shfl_down_sync(0xffffffffu, part, o);
    __shared__ float s[4];
    if ((d & 31) == 0) s[d >> 5] = part;
    __syncthreads();
    const float total = s[0] + s[1] + s[2] + s[3];

    const float ncs = cs[k] * DECAYF + OMDF * g_counts[k];
    if (d == 0) out[NCS_OFF + (size_t)k] = ncs;

    const size_t off = (size_t)k * DDIM + d;
    const float nea = ea[off] * DECAYF + OMDF * g_embed_sum[off];
    out[NEA_OFF + off] = nea;
    const float sm = (ncs + EPSF) / (total + KEPSF) * total;
    out[EMB_OFF + off] = nea / sm;
}

// ---------------------------------------------------------------------------
extern "C" void kernel_launch(void* const* d_in, const int* in_sizes, int n_in,
                              void* d_out, int out_size) {
    const float* x  = (const float*)d_in[0];
    const float* e  = (const float*)d_in[1];
    const float* ea = (const float*)d_in[2];
    const float* cs = (const float*)d_in[3];
    float* out = (float*)d_out;

    k_zero<<<512, 256>>>();                     // idx 0
    k_ee<<<KCODES / 4, 512>>>(e);               // idx 1
    k_packE<<<64, 256>>>(e);                    // idx 2
    k_score<<<N_ROWS / 256, 256>>>(x, e, out);  // idx 3  (ncu capture slot)
    k_cfin<<<KCODES, 128>>>(cs, ea, out);       // idx 4
}

// round 16
// speedup vs baseline: 1.1485x; 1.1485x over previous
#include <cuda_runtime.h>
#include <cuda_bf16.h>
#include <cstdint>
#include <float.h>

// Problem constants
#define N_ROWS  (64 * 2048)   // 131072
#define DDIM    128
#define KCODES  1024

// Output layout (fp32, concatenated in reference return order)
#define Q_OFF    ((size_t)0)
#define IND_OFF  ((size_t)16777216)
#define EMB_OFF  ((size_t)16908288)
#define NCS_OFF  ((size_t)17039360)
#define NEA_OFF  ((size_t)17040384)

#define DECAYF   0.99f
#define OMDF     0.01f
#define EPSF     1e-5f
#define KEPSF    0.01024f

#define SCREEN_T 0.6f
#define CAND_CAP 64

// ---------------------------------------------------------------------------
// Scratch (__device__ globals; no allocation allowed)
__device__ float    g_counts[KCODES];
__device__ float    g_embed_sum[KCODES * DDIM];
__device__ float    g_ee[KCODES];
__device__ uint4    g_E16[KCODES * 16];   // bf16 E, XOR-swizzled 16B units (256 KB)

// ---------------------------------------------------------------------------
// Init: zero accumulators + per-code squared norms + pack E (bf16, swizzled).
// 512 threads = 4 codes per block (128 threads per code).
__global__ void k_init(const float* __restrict__ embed) {
    const int k = blockIdx.x * 4 + (threadIdx.x >> 7);   // code
    const int t = threadIdx.x & 127;
    g_embed_sum[(size_t)k * DDIM + t] = 0.0f;
    if (t == 0) g_counts[k] = 0.0f;

    float v = embed[(size_t)k * DDIM + t];
    v *= v;
    __shared__ float s[16];
    #pragma unroll
    for (int o = 16; o > 0; o >>= 1) v += __shfl_down_sync(0xffffffffu, v, o);
    if ((t & 31) == 0) s[threadIdx.x >> 5] = v;
    __syncthreads();
    if (t == 0) {
        const int b = (threadIdx.x >> 7) * 4;
        g_ee[k] = s[b] + s[b + 1] + s[b + 2] + s[b + 3];
    }

    if (t < 16) {
        const float* src = embed + (size_t)k * DDIM + t * 8;
        float4 a = ((const float4*)src)[0];
        float4 b = ((const float4*)src)[1];
        __nv_bfloat162 p0 = __float22bfloat162_rn(make_float2(a.x, a.y));
        __nv_bfloat162 p1 = __float22bfloat162_rn(make_float2(a.z, a.w));
        __nv_bfloat162 p2 = __float22bfloat162_rn(make_float2(b.x, b.y));
        __nv_bfloat162 p3 = __float22bfloat162_rn(make_float2(b.z, b.w));
        uint4 o4;
        o4.x = *(uint32_t*)&p0; o4.y = *(uint32_t*)&p1;
        o4.z = *(uint32_t*)&p2; o4.w = *(uint32_t*)&p3;
        g_E16[k * 16 + (t ^ (k & 7))] = o4;
    }
}

// ---------------------------------------------------------------------------
__device__ __forceinline__ uint32_t smem_u32(const void* p) {
    uint32_t a;
    asm("{ .reg .u64 t; cvta.to.shared.u64 t, %1; cvt.u32.u64 %0, t; }" : "=r"(a) : "l"(p));
    return a;
}

#define MMA_BF16(accp, af, bb0, bb1) \
    asm volatile( \
        "mma.sync.aligned.m16n8k16.row.col.f32.bf16.bf16.f32 " \
        "{%0,%1,%2,%3}, {%4,%5,%6,%7}, {%8,%9}, {%0,%1,%2,%3};" \
        : "+f"((accp)[0]), "+f"((accp)[1]), "+f"((accp)[2]), "+f"((accp)[3]) \
        : "r"((af)[0]), "r"((af)[1]), "r"((af)[2]), "r"((af)[3]), \
          "r"(bb0), "r"(bb1))

// MMA over one 16-code batch (1 m-tile of 16 rows): fills acc[2][4].
// ldmatrix swizzle offsets uoff[8] precomputed (loop-invariant).
#define BATCH_MMA(b) \
    { \
        const uint32_t rowaddr = smEb + (((b) * 16 + ctile * 8 + row8) << 8); \
        _Pragma("unroll") \
        for (int n2 = 0; n2 < 2; n2++) \
            _Pragma("unroll") \
            for (int i = 0; i < 4; i++) acc[n2][i] = 0.0f; \
        _Pragma("unroll") \
        for (int ks = 0; ks < 8; ks++) { \
            uint32_t b0, b1, b2, b3; \
            asm volatile( \
                "ldmatrix.sync.aligned.m8n8.x4.shared.b16 {%0,%1,%2,%3}, [%4];" \
                : "=r"(b0), "=r"(b1), "=r"(b2), "=r"(b3) \
                : "r"(rowaddr + uoff[ks])); \
            MMA_BF16(acc[0], afr[ks], b0, b1); \
            MMA_BF16(acc[1], afr[ks], b2, b3); \
        } \
    }

// Compute the 8 batch scores into sc[2][4] (ee pairs from float2 smem)
#define BATCH_SCORES(b) \
    _Pragma("unroll") \
    for (int n2 = 0; n2 < 2; n2++) { \
        const float2 ee = sEE2[buf][(b) * 8 + n2 * 4 + tig]; \
        sc[0][n2 * 2 + 0] = fmaf(2.0f, acc[n2][0], -ee.x); \
        sc[0][n2 * 2 + 1] = fmaf(2.0f, acc[n2][1], -ee.y); \
        sc[1][n2 * 2 + 0] = fmaf(2.0f, acc[n2][2], -ee.x); \
        sc[1][n2 * 2 + 1] = fmaf(2.0f, acc[n2][3], -ee.y); \
    }

// Prefetch chunk ch into buffer bf (cp.async, 4x16B per thread + sEE pairs)
#define PREFETCH(ch, bf) \
    { \
        const uint32_t dst = smEbase + (bf) * 16384 + (uint32_t)tid * 16; \
        const uint4* srcp = g_E16 + (ch) * 1024 + tid; \
        _Pragma("unroll") \
        for (int i = 0; i < 4; i++) \
            asm volatile("cp.async.cg.shared.global [%0], [%1], 16;" \
                         :: "r"(dst + i * 4096), "l"(srcp + i * 256) : "memory"); \
        if (tid < 32) sEE2[bf][tid] = ((const float2*)(g_ee + (ch) * 64))[tid]; \
        asm volatile("cp.async.commit_group;" ::: "memory"); \
    }

// ---------------------------------------------------------------------------
// HMMA two-level screening + quad-cooperative exact fp32 rescore + fused
// quantized write and EMA scatter. Double-buffered cp.async E staging.
// CTA = 256 threads (8 warps), each warp owns 16 rows -> CTA covers 128 rows.
__global__ __launch_bounds__(256, 3) void k_score(const float* __restrict__ x,
                                                  const float* __restrict__ embed,
                                                  float* __restrict__ out) {
    __shared__ __align__(16) uint4 smE[2][1024];    // 2 x 16 KB E tiles
    __shared__ float2    sEE2[2][32];
    __shared__ uint16_t  sCand[128 * CAND_CAP];     // 16 KB
    __shared__ uint32_t  sCnt[128];
    __shared__ int       fidx[128];

    const int tid  = threadIdx.x;
    const int wid  = tid >> 5;
    const int lane = tid & 31;
    const int g    = lane >> 2;
    const int tig  = lane & 3;
    const int rbase = blockIdx.x * 128 + wid * 16;

    if (tid < 128) sCnt[tid] = 0;

    const uint32_t smEbase = smem_u32(smE);

    // Prologue: prefetch chunk 0 into buffer 0.
    PREFETCH(0, 0);

    // Build A fragments directly from x (fp32 -> bf16x2). 8 k-steps x 4 regs.
    uint32_t afr[8][4];
    {
        const float* xr0 = x + (size_t)(rbase + g) * DDIM + 2 * tig;
        const float* xr1 = xr0 + 8 * DDIM;
        #pragma unroll
        for (int ks = 0; ks < 8; ks++) {
            const float2 v0 = *(const float2*)(xr0 + 16 * ks);
            const float2 v1 = *(const float2*)(xr1 + 16 * ks);
            const float2 v2 = *(const float2*)(xr0 + 16 * ks + 8);
            const float2 v3 = *(const float2*)(xr1 + 16 * ks + 8);
            __nv_bfloat162 b0 = __float22bfloat162_rn(v0);
            __nv_bfloat162 b1 = __float22bfloat162_rn(v1);
            __nv_bfloat162 b2 = __float22bfloat162_rn(v2);
            __nv_bfloat162 b3 = __float22bfloat162_rn(v3);
            afr[ks][0] = *(uint32_t*)&b0;
            afr[ks][1] = *(uint32_t*)&b1;
            afr[ks][2] = *(uint32_t*)&b2;
            afr[ks][3] = *(uint32_t*)&b3;
        }
    }

    float rmax[2];
    rmax[0] = -FLT_MAX; rmax[1] = -FLT_MAX;

    const int row8  = lane & 7;
    const int ctile = (lane >> 4) & 1;
    const int khalf = (lane >> 3) & 1;

    // Hoisted ldmatrix swizzle offsets (constant across all batches/chunks).
    uint32_t uoff[8];
    #pragma unroll
    for (int ks = 0; ks < 8; ks++)
        uoff[ks] = (uint32_t)(((2 * ks + khalf) ^ row8) << 4);

    for (int c = 0; c < 16; c++) {    // 16 chunks of 64 codes
        const int buf = c & 1;
        asm volatile("cp.async.wait_group 0;" ::: "memory");
        __syncthreads();              // buffer `buf` ready; buffer buf^1 free
        if (c < 15) PREFETCH(c + 1, buf ^ 1);

        const uint32_t smEb = smEbase + buf * 16384;
        float acc[2][4];
        float sc[2][4];

        if (c == 0) {
            // Max-only warm-up over chunk 0 (no appends).
            #pragma unroll
            for (int b = 0; b < 4; b++) {
                BATCH_MMA(b);
                BATCH_SCORES(b);
                #pragma unroll
                for (int h = 0; h < 2; h++)
                    rmax[h] = fmaxf(rmax[h],
                                    fmaxf(fmaxf(sc[h][0], sc[h][1]),
                                          fmaxf(sc[h][2], sc[h][3])));
            }
            #pragma unroll
            for (int i = 0; i < 2; i++) {
                float v = rmax[i];
                v = fmaxf(v, __shfl_xor_sync(0xffffffffu, v, 1));
                v = fmaxf(v, __shfl_xor_sync(0xffffffffu, v, 2));
                rmax[i] = v;
            }
        }

        #pragma unroll
        for (int b = 0; b < 4; b++) {
            BATCH_MMA(b);
            BATCH_SCORES(b);

            // Two-level screening: compare the per-row batch max once.
            #pragma unroll
            for (int h = 0; h < 2; h++) {
                const float thr = rmax[h] - SCREEN_T;
                const float m = fmaxf(fmaxf(sc[h][0], sc[h][1]),
                                      fmaxf(sc[h][2], sc[h][3]));
                if (m >= thr) {    // rare
                    const int lr = wid * 16 + h * 8 + g;
                    #pragma unroll
                    for (int n2 = 0; n2 < 2; n2++)
                        #pragma unroll
                        for (int j = 0; j < 2; j++)
                            if (sc[h][n2 * 2 + j] >= thr) {
                                uint32_t n = atomicAdd(&sCnt[lr], 1u);
                                if (n < CAND_CAP)
                                    sCand[lr * CAND_CAP + n] =
                                        (uint16_t)(c * 64 + b * 16 + n2 * 8 + 2 * tig + j);
                            }
                }
                rmax[h] = fmaxf(rmax[h], m);
            }
        }

        #pragma unroll
        for (int i = 0; i < 2; i++) {
            float v = rmax[i];
            v = fmaxf(v, __shfl_xor_sync(0xffffffffu, v, 1));
            v = fmaxf(v, __shfl_xor_sync(0xffffffffu, v, 2));
            rmax[i] = v;
        }
    }
    __syncthreads();

    // Exact fp32 rescore: 8-lane quad per candidate.
    // dist' = 2*dot - ee (the -xx term is row-constant: argmax-equivalent).
    {
        const int ql = lane & 7;
        const int q  = lane >> 3;
        for (int rr = 0; rr < 16; rr++) {
            const int lr  = wid * 16 + rr;
            const int row = blockIdx.x * 128 + lr;
            const int cnt = (int)sCnt[lr];

            float bestv = -FLT_MAX;
            int   bestk = 0x7FFFFFFF;

            if (cnt <= CAND_CAP) {
                float4 xa[4];
                const float4* xr = (const float4*)(x + (size_t)row * DDIM);
                #pragma unroll
                for (int it = 0; it < 4; it++) xa[it] = xr[it * 8 + ql];

                for (int j0 = 0; j0 < cnt; j0 += 4) {
                    const int j  = j0 + q;
                    const int jc = (j < cnt) ? j : (cnt - 1);
                    const int kq = sCand[lr * CAND_CAP + jc];
                    const float4* er = (const float4*)(embed + (size_t)kq * DDIM);
                    float a0 = 0.f, a1 = 0.f, a2 = 0.f, a3 = 0.f;
                    #pragma unroll
                    for (int it = 0; it < 4; it++) {
                        const float4 ea = er[it * 8 + ql];
                        a0 = fmaf(xa[it].x, ea.x, a0);
                        a1 = fmaf(xa[it].y, ea.y, a1);
                        a2 = fmaf(xa[it].z, ea.z, a2);
                        a3 = fmaf(xa[it].w, ea.w, a3);
                    }
                    float part = (a0 + a1) + (a2 + a3);
                    part += __shfl_xor_sync(0xffffffffu, part, 1);
                    part += __shfl_xor_sync(0xffffffffu, part, 2);
                    part += __shfl_xor_sync(0xffffffffu, part, 4);
                    const float dist = 2.0f * part - g_ee[kq];
                    if (j < cnt &&
                        (dist > bestv || (dist == bestv && kq < bestk))) {
                        bestv = dist; bestk = kq;
                    }
                }
            } else {
                const float4* xr = (const float4*)(x + (size_t)row * DDIM);
                for (int k = lane; k < KCODES; k += 32) {
                    const float4* er = (const float4*)(embed + (size_t)k * DDIM);
                    float a0 = 0.f, a1 = 0.f, a2 = 0.f, a3 = 0.f;
                    #pragma unroll 8
                    for (int i = 0; i < 32; i++) {
                        float4 va = xr[i], ea = er[i];
                        a0 = fmaf(va.x, ea.x, a0);
                        a1 = fmaf(va.y, ea.y, a1);
                        a2 = fmaf(va.z, ea.z, a2);
                        a3 = fmaf(va.w, ea.w, a3);
                    }
                    const float dist = 2.0f * ((a0 + a1) + (a2 + a3)) - g_ee[k];
                    if (dist > bestv || (dist == bestv && k < bestk)) {
                        bestv = dist; bestk = k;
                    }
                }
                #pragma unroll
                for (int o = 1; o <= 4; o <<= 1) {
                    const float ov = __shfl_xor_sync(0xffffffffu, bestv, o);
                    const int   ok = __shfl_xor_sync(0xffffffffu, bestk, o);
                    if (ov > bestv || (ov == bestv && ok < bestk)) { bestv = ov; bestk = ok; }
                }
            }

            #pragma unroll
            for (int o = 8; o <= 16; o <<= 1) {
                const float ov = __shfl_xor_sync(0xffffffffu, bestv, o);
                const int   ok = __shfl_xor_sync(0xffffffffu, bestk, o);
                if (ov > bestv || (ov == bestv && ok < bestk)) { bestv = ov; bestk = ok; }
            }
            if (lane == 0) fidx[lr] = bestk;
        }
    }
    __syncthreads();

    // Coalesced embed_ind write from fidx.
    if (tid < 128)
        out[IND_OFF + (size_t)(blockIdx.x * 128 + tid)] = (float)fidx[tid];

    // Fused epilogue: quantized = embed[idx] write + EMA scatter (RED).
    for (int v = tid; v < 128 * 32; v += 256) {
        const int r = v >> 5, seg = v & 31;
        const int idx = fidx[r];
        const float4* ep = (const float4*)(embed + (size_t)idx * DDIM);
        ((float4*)out)[(size_t)(blockIdx.x * 128 + r) * 32 + seg] = ep[seg];

        const float4 xv =
            ((const float4*)(x + (size_t)(blockIdx.x * 128 + r) * DDIM))[seg];
        float* dst = &g_embed_sum[(size_t)idx * DDIM + seg * 4];
        asm volatile("red.global.add.v4.f32 [%0], {%1,%2,%3,%4};"
                     :: "l"(dst), "f"(xv.x), "f"(xv.y), "f"(xv.z), "f"(xv.w)
                     : "memory");
    }
    if (tid < 128) atomicAdd(&g_counts[fidx[tid]], 1.0f);
}

// ---------------------------------------------------------------------------
// Final epilogue: new_cluster_size (+ redundant per-block total), new_embed_avg,
// new_embed. Block k handles code k.
__global__ void k_cfin(const float* __restrict__ cs,
                       const float* __restrict__ ea,
                       float* __restrict__ out) {
    const int k = blockIdx.x;    // 1024
    const int d = threadIdx.x;   // 128

    float part = 0.0f;
    #pragma unroll
    for (int i = 0; i < 8; i++) {
        const int j = d + i * 128;
        part += cs[j] * DECAYF + OMDF * g_counts[j];
    }
    #pragma unroll
    for (int o = 16; o > 0; o >>= 1) part += __shfl_down_sync(0xffffffffu, part, o);
    __shared__ float s[4];
    if ((d & 31) == 0) s[d >> 5] = part;
    __syncthreads();
    const float total = s[0] + s[1] + s[2] + s[3];

    const float ncs = cs[k] * DECAYF + OMDF * g_counts[k];
    if (d == 0) out[NCS_OFF + (size_t)k] = ncs;

    const size_t off = (size_t)k * DDIM + d;
    const float nea = ea[off] * DECAYF + OMDF * g_embed_sum[off];
    out[NEA_OFF + off] = nea;
    const float sm = (ncs + EPSF) / (total + KEPSF) * total;
    out[EMB_OFF + off] = nea / sm;
}

// ---------------------------------------------------------------------------
extern "C" void kernel_launch(void* const* d_in, const int* in_sizes, int n_in,
                              void* d_out, int out_size) {
    const float* x  = (const float*)d_in[0];
    const float* e  = (const float*)d_in[1];
    const float* ea = (const float*)d_in[2];
    const float* cs = (const float*)d_in[3];
    float* out = (float*)d_out;

    k_init<<<KCODES / 4, 512>>>(e);             // launch 1 (init + packE)
    k_score<<<N_ROWS / 128, 256>>>(x, e, out);  // launch 2 (everything per-row)
    k_cfin<<<KCODES, 128>>>(cs, ea, out);       // launch 3 (EMA epilogue)
}